// round 3
// baseline (speedup 1.0000x reference)
#include <cuda_runtime.h>
#include <cstdint>

#define NMAX 50000
#define H 128

// Scratch (no allocs allowed -> __device__ globals; float4 for 16B alignment)
__device__ float4 g_nbW2[NMAX * (H / 4)];   // node_embedding @ W2
__device__ float4 g_accum[NMAX * (H / 4)];  // scatter-sum of nbW2[col] into row
__device__ float  g_s[NMAX];                // per-node sum of edge_attr
__device__ float4 g_v3[H / 4];              // relu(W4) @ W3

// ---------------------------------------------------------------------------
// Zero accumulators
// ---------------------------------------------------------------------------
__global__ void zero_kernel(int n) {
    int idx = blockIdx.x * blockDim.x + threadIdx.x;
    float4 z = make_float4(0.f, 0.f, 0.f, 0.f);
    if (idx < n * (H / 4)) g_accum[idx] = z;
    if (idx < n) g_s[idx] = 0.f;
}

// ---------------------------------------------------------------------------
// v3[j] = sum_c relu(W4[c]) * W3[c][j]   (one block, 128 threads)
// ---------------------------------------------------------------------------
__global__ void v3_kernel(const float* __restrict__ W4,
                          const float* __restrict__ W3) {
    int j = threadIdx.x;
    float acc = 0.f;
#pragma unroll 8
    for (int c = 0; c < H; ++c) {
        float w = W4[c];
        w = w > 0.f ? w : 0.f;
        acc += w * W3[c * H + j];
    }
    ((float*)g_v3)[j] = acc;
}

// ---------------------------------------------------------------------------
// nbW2 = node_embedding[N,128] @ W2[128,128]  (fp32, register-tiled)
// Block: 256 threads, 64 rows x 128 cols per block.
// ---------------------------------------------------------------------------
__global__ void gemm_nbW2_kernel(const float* __restrict__ nb,
                                 const float* __restrict__ W2, int n) {
    extern __shared__ float sm[];
    float* Bs = sm;            // [128][128]
    float* As = sm + H * H;    // [128][64]  (k-major)
    const int t = threadIdx.x;
    const int rbase = blockIdx.x * 64;

    for (int i = t; i < H * H / 4; i += 256)
        ((float4*)Bs)[i] = ((const float4*)W2)[i];

    for (int i = t; i < 64 * 32; i += 256) {
        int row = i >> 5;   // 0..63
        int kq  = i & 31;   // float4 index along k
        int r = rbase + row;
        float4 v = (r < n) ? ((const float4*)nb)[r * 32 + kq]
                           : make_float4(0.f, 0.f, 0.f, 0.f);
        As[(4 * kq + 0) * 64 + row] = v.x;
        As[(4 * kq + 1) * 64 + row] = v.y;
        As[(4 * kq + 2) * 64 + row] = v.z;
        As[(4 * kq + 3) * 64 + row] = v.w;
    }
    __syncthreads();

    const int lane = t & 31;
    const int wid  = t >> 5;
    const int r0   = wid * 8;
    const int c0   = lane * 4;

    float4 acc[8];
#pragma unroll
    for (int j = 0; j < 8; ++j) acc[j] = make_float4(0.f, 0.f, 0.f, 0.f);

#pragma unroll 4
    for (int k = 0; k < H; ++k) {
        float4 b  = *(const float4*)&Bs[k * H + c0];
        float4 a0 = *(const float4*)&As[k * 64 + r0];
        float4 a1 = *(const float4*)&As[k * 64 + r0 + 4];
        float a[8] = {a0.x, a0.y, a0.z, a0.w, a1.x, a1.y, a1.z, a1.w};
#pragma unroll
        for (int j = 0; j < 8; ++j) {
            acc[j].x += a[j] * b.x;
            acc[j].y += a[j] * b.y;
            acc[j].z += a[j] * b.z;
            acc[j].w += a[j] * b.w;
        }
    }

#pragma unroll
    for (int j = 0; j < 8; ++j) {
        int r = rbase + r0 + j;
        if (r < n) g_nbW2[r * 32 + (c0 >> 2)] = acc[j];
    }
}

// ---------------------------------------------------------------------------
// Edge scatter: one warp per edge. Handles int32 OR int64 edge_index.
//   accum[row] += nbW2[col]  (red.global.add.v4.f32, 16B per lane)
//   s[row]     += edge_attr[e]  (lane 0)
// ---------------------------------------------------------------------------
__global__ void scatter_kernel(const void* __restrict__ ei_raw,
                               const float* __restrict__ ea, int e, int n) {
    int gw   = (blockIdx.x * blockDim.x + threadIdx.x) >> 5;
    int lane = threadIdx.x & 31;
    if (gw >= e) return;

    const int* ei32 = (const int*)ei_raw;
    // int64 little-endian with values < 2^31 -> every odd 32-bit word is 0.
    bool is64 = (ei32[1] | ei32[3] | ei32[5] | ei32[7]) == 0;

    int r, c;
    if (is64) {
        const long long* ei64 = (const long long*)ei_raw;
        r = (int)ei64[gw];
        c = (int)ei64[e + gw];
    } else {
        r = ei32[gw];
        c = ei32[e + gw];
    }
    if ((unsigned)r >= (unsigned)n || (unsigned)c >= (unsigned)n) return;

    const float4 v = g_nbW2[c * 32 + lane];
    float4* dst = &g_accum[r * 32 + lane];
    asm volatile("red.global.add.v4.f32 [%0], {%1,%2,%3,%4};"
                 :: "l"(dst), "f"(v.x), "f"(v.y), "f"(v.z), "f"(v.w)
                 : "memory");
    if (lane == 0) atomicAdd(&g_s[r], ea[gw]);
}

// ---------------------------------------------------------------------------
// Epilogue: out[r][c] = relu( (x@W1)[r][c] + accum[r][c] + s[r]*v3[c] )
// ---------------------------------------------------------------------------
__global__ void epilogue_kernel(const float* __restrict__ x,
                                const float* __restrict__ W1,
                                float* __restrict__ out, int n) {
    int g = blockIdx.x * blockDim.x + threadIdx.x;
    int r = g >> 5;
    int q = g & 31;
    if (r >= n) return;

    float4 acc = g_accum[r * 32 + q];
    float  s   = g_s[r];
    float4 v   = g_v3[q];
    acc.x += s * v.x; acc.y += s * v.y; acc.z += s * v.z; acc.w += s * v.w;

    float4 xv0 = ((const float4*)x)[r * 2];
    float4 xv1 = ((const float4*)x)[r * 2 + 1];
    float xk[8] = {xv0.x, xv0.y, xv0.z, xv0.w, xv1.x, xv1.y, xv1.z, xv1.w};
#pragma unroll
    for (int k = 0; k < 8; ++k) {
        float4 w = ((const float4*)W1)[k * 32 + q];
        acc.x += xk[k] * w.x;
        acc.y += xk[k] * w.y;
        acc.z += xk[k] * w.z;
        acc.w += xk[k] * w.w;
    }
    acc.x = acc.x > 0.f ? acc.x : 0.f;
    acc.y = acc.y > 0.f ? acc.y : 0.f;
    acc.z = acc.z > 0.f ? acc.z : 0.f;
    acc.w = acc.w > 0.f ? acc.w : 0.f;
    ((float4*)out)[r * 32 + q] = acc;
}

// ---------------------------------------------------------------------------
extern "C" void kernel_launch(void* const* d_in, const int* in_sizes, int n_in,
                              void* d_out, int out_size) {
    const float* x   = (const float*)d_in[0];
    const void*  ei  = d_in[1];                 // int32 or int64, detected on device
    const float* ea  = (const float*)d_in[2];
    const float* nb  = (const float*)d_in[3];
    const float* W1  = (const float*)d_in[4];
    const float* W2  = (const float*)d_in[5];
    const float* W3  = (const float*)d_in[6];
    const float* W4  = (const float*)d_in[7];
    float* out = (float*)d_out;

    const int n = in_sizes[0] / 8;   // 50000
    const int e = in_sizes[2];       // 800000

    const int smem = (H * H + H * 64) * sizeof(float);  // 98304 B
    cudaFuncSetAttribute(gemm_nbW2_kernel,
                         cudaFuncAttributeMaxDynamicSharedMemorySize, smem);

    int zero_blocks = (n * 32 + 255) / 256;
    zero_kernel<<<zero_blocks, 256>>>(n);

    v3_kernel<<<1, 128>>>(W4, W3);

    int gemm_blocks = (n + 63) / 64;
    gemm_nbW2_kernel<<<gemm_blocks, 256, smem>>>(nb, W2, n);

    int scat_blocks = (e * 32 + 255) / 256;
    scatter_kernel<<<scat_blocks, 256>>>(ei, ea, e, n);

    int epi_blocks = (n * 32 + 255) / 256;
    epilogue_kernel<<<epi_blocks, 256>>>(x, W1, out, n);
}

// round 4
// speedup vs baseline: 1.4792x; 1.4792x over previous
#include <cuda_runtime.h>
#include <cstdint>

#define NMAX 50000
#define EMAX 800000
#define H 128
#define SCAN_B 256

// ---------------- scratch (__device__ globals; float4 => 16B aligned) -------
__device__ float4 g_aggr[NMAX * (H / 4)];  // segment-sum of node_embedding rows
__device__ float  g_s[NMAX];               // per-node sum of edge_attr
__device__ float4 g_v3[H / 4];             // relu(W4) @ W3
__device__ int    g_cnt[NMAX];             // degree counts, then fill cursors
__device__ int    g_off[NMAX + 1];         // CSR row offsets
__device__ int    g_bsum[SCAN_B];          // per-block sums for scan
__device__ int    g_cols[EMAX];            // CSR column indices
__device__ float  g_eas[EMAX];             // CSR-permuted edge_attr

// ---------------------------------------------------------------------------
__device__ __forceinline__ void load_edge(const void* __restrict__ ei, int e,
                                          int idx, int& r, int& c) {
    const int* p32 = (const int*)ei;
    // int64 little-endian with values < 2^31 -> odd 32-bit words are 0
    bool is64 = (p32[1] | p32[3] | p32[5] | p32[7]) == 0;
    if (is64) {
        const long long* p64 = (const long long*)ei;
        r = (int)p64[idx];
        c = (int)p64[e + idx];
    } else {
        r = p32[idx];
        c = p32[e + idx];
    }
}

// ---------------------------------------------------------------------------
__global__ void zero_cnt_kernel(int n) {
    int i = blockIdx.x * blockDim.x + threadIdx.x;
    if (i < n) g_cnt[i] = 0;
}

__global__ void hist_kernel(const void* __restrict__ ei, int e, int n) {
    int i = blockIdx.x * blockDim.x + threadIdx.x;
    if (i >= e) return;
    int r, c;
    load_edge(ei, e, i, r, c);
    if ((unsigned)r < (unsigned)n) atomicAdd(&g_cnt[r], 1);
}

// scan phase 1: per-block sums of g_cnt
__global__ void scan1_kernel(int n) {
    __shared__ int sm[SCAN_B];
    int t = threadIdx.x;
    int i = blockIdx.x * SCAN_B + t;
    sm[t] = (i < n) ? g_cnt[i] : 0;
    __syncthreads();
    for (int d = SCAN_B / 2; d > 0; d >>= 1) {
        if (t < d) sm[t] += sm[t + d];
        __syncthreads();
    }
    if (t == 0) g_bsum[blockIdx.x] = sm[0];
}

// scan phase 2: exclusive scan of block sums (single block; nb <= SCAN_B)
__global__ void scan2_kernel(int nb, int n) {
    __shared__ int sm[SCAN_B];
    int t = threadIdx.x;
    int v = (t < nb) ? g_bsum[t] : 0;
    sm[t] = v;
    __syncthreads();
    for (int d = 1; d < SCAN_B; d <<= 1) {
        int x = (t >= d) ? sm[t - d] : 0;
        __syncthreads();
        sm[t] += x;
        __syncthreads();
    }
    if (t < nb) g_bsum[t] = sm[t] - v;           // exclusive
    if (t == SCAN_B - 1) g_off[n] = sm[t];       // total
}

// scan phase 3: per-block exclusive scan + base; write offsets & cursors
__global__ void scan3_kernel(int n) {
    __shared__ int sm[SCAN_B];
    int t = threadIdx.x;
    int i = blockIdx.x * SCAN_B + t;
    int v = (i < n) ? g_cnt[i] : 0;
    sm[t] = v;
    __syncthreads();
    for (int d = 1; d < SCAN_B; d <<= 1) {
        int x = (t >= d) ? sm[t - d] : 0;
        __syncthreads();
        sm[t] += x;
        __syncthreads();
    }
    if (i < n) {
        int excl = sm[t] - v + g_bsum[blockIdx.x];
        g_off[i] = excl;
        g_cnt[i] = excl;  // cursor for fill
    }
}

__global__ void fill_kernel(const void* __restrict__ ei,
                            const float* __restrict__ ea, int e, int n) {
    int i = blockIdx.x * blockDim.x + threadIdx.x;
    if (i >= e) return;
    int r, c;
    load_edge(ei, e, i, r, c);
    if ((unsigned)r >= (unsigned)n || (unsigned)c >= (unsigned)n) return;
    int pos = atomicAdd(&g_cnt[r], 1);
    g_cols[pos] = c;
    g_eas[pos] = ea[i];
}

// ---------------------------------------------------------------------------
// v3[j] = sum_c relu(W4[c]) * W3[c][j]
// ---------------------------------------------------------------------------
__global__ void v3_kernel(const float* __restrict__ W4,
                          const float* __restrict__ W3) {
    int j = threadIdx.x;
    float acc = 0.f;
#pragma unroll 8
    for (int c = 0; c < H; ++c) {
        float w = W4[c];
        w = w > 0.f ? w : 0.f;
        acc += w * W3[c * H + j];
    }
    ((float*)g_v3)[j] = acc;
}

// ---------------------------------------------------------------------------
// Aggregate: warp per row. acc += nb[col] over CSR row; s = sum(ea).
// Lane l owns cols [4l, 4l+4). Gathers coalesced (512B/warp), no atomics.
// ---------------------------------------------------------------------------
__global__ void aggr_kernel(const float* __restrict__ nb, int n) {
    int w    = (blockIdx.x * blockDim.x + threadIdx.x) >> 5;
    int lane = threadIdx.x & 31;
    if (w >= n) return;

    const float4* nb4 = (const float4*)nb;
    int beg = g_off[w], end = g_off[w + 1];

    float4 acc = make_float4(0.f, 0.f, 0.f, 0.f);
    float  s   = 0.f;
    int j = beg;
    for (; j + 4 <= end; j += 4) {
        int c0 = g_cols[j], c1 = g_cols[j + 1], c2 = g_cols[j + 2], c3 = g_cols[j + 3];
        float4 v0 = nb4[c0 * 32 + lane];
        float4 v1 = nb4[c1 * 32 + lane];
        float4 v2 = nb4[c2 * 32 + lane];
        float4 v3v = nb4[c3 * 32 + lane];
        acc.x += (v0.x + v1.x) + (v2.x + v3v.x);
        acc.y += (v0.y + v1.y) + (v2.y + v3v.y);
        acc.z += (v0.z + v1.z) + (v2.z + v3v.z);
        acc.w += (v0.w + v1.w) + (v2.w + v3v.w);
        if (lane == 0)
            s += (g_eas[j] + g_eas[j + 1]) + (g_eas[j + 2] + g_eas[j + 3]);
    }
    for (; j < end; ++j) {
        int c = g_cols[j];
        float4 v = nb4[c * 32 + lane];
        acc.x += v.x; acc.y += v.y; acc.z += v.z; acc.w += v.w;
        if (lane == 0) s += g_eas[j];
    }
    g_aggr[w * 32 + lane] = acc;
    if (lane == 0) g_s[w] = s;
}

// ---------------------------------------------------------------------------
// Fused GEMM + epilogue:
//   out = relu( x@W1 + aggr@W2 + s*v3 )
// Block: 256 threads, 64 rows x 128 cols. Smem: W2 (64KB) + aggr tile^T (32KB).
// ---------------------------------------------------------------------------
__global__ void gemm_fused_kernel(const float* __restrict__ x,
                                  const float* __restrict__ W1,
                                  const float* __restrict__ W2,
                                  float* __restrict__ out, int n) {
    extern __shared__ float sm[];
    float* Bs = sm;            // [128][128] = W2
    float* As = sm + H * H;    // [128][64]  = aggr tile (k-major)
    const int t = threadIdx.x;
    const int rbase = blockIdx.x * 64;

    for (int i = t; i < H * H / 4; i += 256)
        ((float4*)Bs)[i] = ((const float4*)W2)[i];

    for (int i = t; i < 64 * 32; i += 256) {
        int row = i >> 5;
        int kq  = i & 31;
        int r = rbase + row;
        float4 v = (r < n) ? g_aggr[r * 32 + kq]
                           : make_float4(0.f, 0.f, 0.f, 0.f);
        As[(4 * kq + 0) * 64 + row] = v.x;
        As[(4 * kq + 1) * 64 + row] = v.y;
        As[(4 * kq + 2) * 64 + row] = v.z;
        As[(4 * kq + 3) * 64 + row] = v.w;
    }
    __syncthreads();

    const int lane = t & 31;
    const int wid  = t >> 5;
    const int r0   = wid * 8;
    const int c0   = lane * 4;

    float4 acc[8];
#pragma unroll
    for (int j = 0; j < 8; ++j) acc[j] = make_float4(0.f, 0.f, 0.f, 0.f);

#pragma unroll 4
    for (int k = 0; k < H; ++k) {
        float4 b  = *(const float4*)&Bs[k * H + c0];
        float4 a0 = *(const float4*)&As[k * 64 + r0];
        float4 a1 = *(const float4*)&As[k * 64 + r0 + 4];
        float a[8] = {a0.x, a0.y, a0.z, a0.w, a1.x, a1.y, a1.z, a1.w};
#pragma unroll
        for (int j = 0; j < 8; ++j) {
            acc[j].x += a[j] * b.x;
            acc[j].y += a[j] * b.y;
            acc[j].z += a[j] * b.z;
            acc[j].w += a[j] * b.w;
        }
    }

    // epilogue: + x@W1 + s*v3, relu, store
    float4 v3v = g_v3[lane];
#pragma unroll
    for (int j = 0; j < 8; ++j) {
        int r = rbase + r0 + j;
        if (r >= n) break;
        float4 o = acc[j];
        float  s = g_s[r];
        o.x += s * v3v.x; o.y += s * v3v.y; o.z += s * v3v.z; o.w += s * v3v.w;

        float4 xv0 = ((const float4*)x)[r * 2];
        float4 xv1 = ((const float4*)x)[r * 2 + 1];
        float xk[8] = {xv0.x, xv0.y, xv0.z, xv0.w, xv1.x, xv1.y, xv1.z, xv1.w};
#pragma unroll
        for (int k = 0; k < 8; ++k) {
            float4 wv = ((const float4*)W1)[k * 32 + lane];
            o.x += xk[k] * wv.x;
            o.y += xk[k] * wv.y;
            o.z += xk[k] * wv.z;
            o.w += xk[k] * wv.w;
        }
        o.x = o.x > 0.f ? o.x : 0.f;
        o.y = o.y > 0.f ? o.y : 0.f;
        o.z = o.z > 0.f ? o.z : 0.f;
        o.w = o.w > 0.f ? o.w : 0.f;
        ((float4*)out)[r * 32 + lane] = o;
    }
}

// ---------------------------------------------------------------------------
extern "C" void kernel_launch(void* const* d_in, const int* in_sizes, int n_in,
                              void* d_out, int out_size) {
    const float* x   = (const float*)d_in[0];
    const void*  ei  = d_in[1];                 // int32 or int64 (device-detected)
    const float* ea  = (const float*)d_in[2];
    const float* nb  = (const float*)d_in[3];
    const float* W1  = (const float*)d_in[4];
    const float* W2  = (const float*)d_in[5];
    const float* W3  = (const float*)d_in[6];
    const float* W4  = (const float*)d_in[7];
    float* out = (float*)d_out;

    const int n = in_sizes[0] / 8;   // 50000
    const int e = in_sizes[2];       // 800000
    const int nb_scan = (n + SCAN_B - 1) / SCAN_B;   // 196 <= 256

    const int smem = (H * H + H * 64) * sizeof(float);  // 98304 B
    cudaFuncSetAttribute(gemm_fused_kernel,
                         cudaFuncAttributeMaxDynamicSharedMemorySize, smem);

    zero_cnt_kernel<<<(n + 255) / 256, 256>>>(n);
    v3_kernel<<<1, 128>>>(W4, W3);
    hist_kernel<<<(e + 255) / 256, 256>>>(ei, e, n);
    scan1_kernel<<<nb_scan, SCAN_B>>>(n);
    scan2_kernel<<<1, SCAN_B>>>(nb_scan, n);
    scan3_kernel<<<nb_scan, SCAN_B>>>(n);
    fill_kernel<<<(e + 255) / 256, 256>>>(ei, ea, e, n);

    int aggr_blocks = (n * 32 + 255) / 256;
    aggr_kernel<<<aggr_blocks, 256>>>(nb, n);

    gemm_fused_kernel<<<(n + 63) / 64, 256, smem>>>(x, W1, W2, out, n);
}

// round 5
// speedup vs baseline: 1.5426x; 1.0428x over previous
#include <cuda_runtime.h>
#include <cstdint>

#define NMAX 50000
#define EMAX 800000
#define H 128
#define SCAN_B 256

// ---------------- scratch (__device__ globals; float4 => 16B aligned) -------
__device__ float4 g_aggr[NMAX * (H / 4)];  // segment-sum of node_embedding rows
__device__ float  g_s[NMAX];               // per-node sum of edge_attr
__device__ float4 g_v3[H / 4];             // relu(W4) @ W3
__device__ int    g_cnt[NMAX];             // degree counts, then fill cursors
__device__ int    g_off[NMAX + 1];         // CSR row offsets
__device__ int    g_bsum[SCAN_B];          // per-block sums for scan
__device__ int    g_cols[EMAX];            // CSR column indices
__device__ float  g_eas[EMAX];             // CSR-permuted edge_attr

// ---------------------------------------------------------------------------
__device__ __forceinline__ unsigned long long pack2(float v) {
    unsigned long long r;
    asm("mov.b64 %0, {%1, %1};" : "=l"(r) : "f"(v));
    return r;
}
__device__ __forceinline__ void unpack2(unsigned long long p, float& lo, float& hi) {
    asm("mov.b64 {%0, %1}, %2;" : "=f"(lo), "=f"(hi) : "l"(p));
}
__device__ __forceinline__ void ffma2(unsigned long long& d,
                                      unsigned long long a,
                                      unsigned long long b) {
    asm("fma.rn.f32x2 %0, %1, %2, %0;" : "+l"(d) : "l"(a), "l"(b));
}

// ---------------------------------------------------------------------------
__device__ __forceinline__ void load_edge(const void* __restrict__ ei, int e,
                                          int idx, int& r, int& c) {
    const int* p32 = (const int*)ei;
    // int64 little-endian with values < 2^31 -> odd 32-bit words are 0
    bool is64 = (p32[1] | p32[3] | p32[5] | p32[7]) == 0;
    if (is64) {
        const long long* p64 = (const long long*)ei;
        r = (int)p64[idx];
        c = (int)p64[e + idx];
    } else {
        r = p32[idx];
        c = p32[e + idx];
    }
}

// ---------------------------------------------------------------------------
__global__ void zero_cnt_kernel(int n) {
    int i = blockIdx.x * blockDim.x + threadIdx.x;
    if (i < n) g_cnt[i] = 0;
}

__global__ void hist_kernel(const void* __restrict__ ei, int e, int n) {
    int i = blockIdx.x * blockDim.x + threadIdx.x;
    if (i >= e) return;
    int r, c;
    load_edge(ei, e, i, r, c);
    if ((unsigned)r < (unsigned)n) atomicAdd(&g_cnt[r], 1);
}

// scan phase 1: per-block sums of g_cnt
__global__ void scan1_kernel(int n) {
    __shared__ int sm[SCAN_B];
    int t = threadIdx.x;
    int i = blockIdx.x * SCAN_B + t;
    sm[t] = (i < n) ? g_cnt[i] : 0;
    __syncthreads();
    for (int d = SCAN_B / 2; d > 0; d >>= 1) {
        if (t < d) sm[t] += sm[t + d];
        __syncthreads();
    }
    if (t == 0) g_bsum[blockIdx.x] = sm[0];
}

// scan phase 2 (fused): every block scans the block sums itself, then does its
// local exclusive scan + base; writes offsets & fill cursors.
__global__ void scan3_kernel(int n, int nb) {
    __shared__ int sm[SCAN_B];
    int t = threadIdx.x;
    int i = blockIdx.x * SCAN_B + t;

    // scan block sums (nb <= SCAN_B)
    int bv = (t < nb) ? g_bsum[t] : 0;
    sm[t] = bv;
    __syncthreads();
    for (int d = 1; d < SCAN_B; d <<= 1) {
        int xv = (t >= d) ? sm[t - d] : 0;
        __syncthreads();
        sm[t] += xv;
        __syncthreads();
    }
    int base  = (blockIdx.x == 0) ? 0 : sm[blockIdx.x - 1];
    int total = sm[nb - 1];
    __syncthreads();

    // local scan of this block's counts
    int v = (i < n) ? g_cnt[i] : 0;
    sm[t] = v;
    __syncthreads();
    for (int d = 1; d < SCAN_B; d <<= 1) {
        int xv = (t >= d) ? sm[t - d] : 0;
        __syncthreads();
        sm[t] += xv;
        __syncthreads();
    }
    if (i < n) {
        int excl = sm[t] - v + base;
        g_off[i] = excl;
        g_cnt[i] = excl;  // cursor for fill
    }
    if (blockIdx.x == 0 && t == 0) g_off[n] = total;
}

__global__ void fill_kernel(const void* __restrict__ ei,
                            const float* __restrict__ ea, int e, int n) {
    int i = blockIdx.x * blockDim.x + threadIdx.x;
    if (i >= e) return;
    int r, c;
    load_edge(ei, e, i, r, c);
    if ((unsigned)r >= (unsigned)n || (unsigned)c >= (unsigned)n) return;
    int pos = atomicAdd(&g_cnt[r], 1);
    g_cols[pos] = c;
    g_eas[pos] = ea[i];
}

// ---------------------------------------------------------------------------
// v3[j] = sum_c relu(W4[c]) * W3[c][j]
// ---------------------------------------------------------------------------
__global__ void v3_kernel(const float* __restrict__ W4,
                          const float* __restrict__ W3) {
    int j = threadIdx.x;
    float acc = 0.f;
#pragma unroll 8
    for (int c = 0; c < H; ++c) {
        float w = W4[c];
        w = w > 0.f ? w : 0.f;
        acc += w * W3[c * H + j];
    }
    ((float*)g_v3)[j] = acc;
}

// ---------------------------------------------------------------------------
// Aggregate: warp per row. acc += nb[col] over CSR row; s = sum(ea).
// ---------------------------------------------------------------------------
__global__ void aggr_kernel(const float* __restrict__ nb, int n) {
    int w    = (blockIdx.x * blockDim.x + threadIdx.x) >> 5;
    int lane = threadIdx.x & 31;
    if (w >= n) return;

    const float4* nb4 = (const float4*)nb;
    int beg = g_off[w], end = g_off[w + 1];

    float4 acc = make_float4(0.f, 0.f, 0.f, 0.f);
    float  s   = 0.f;
    int j = beg;
    for (; j + 4 <= end; j += 4) {
        int c0 = g_cols[j], c1 = g_cols[j + 1], c2 = g_cols[j + 2], c3 = g_cols[j + 3];
        float4 v0 = nb4[c0 * 32 + lane];
        float4 v1 = nb4[c1 * 32 + lane];
        float4 v2 = nb4[c2 * 32 + lane];
        float4 v3v = nb4[c3 * 32 + lane];
        acc.x += (v0.x + v1.x) + (v2.x + v3v.x);
        acc.y += (v0.y + v1.y) + (v2.y + v3v.y);
        acc.z += (v0.z + v1.z) + (v2.z + v3v.z);
        acc.w += (v0.w + v1.w) + (v2.w + v3v.w);
        if (lane == 0)
            s += (g_eas[j] + g_eas[j + 1]) + (g_eas[j + 2] + g_eas[j + 3]);
    }
    for (; j < end; ++j) {
        int c = g_cols[j];
        float4 v = nb4[c * 32 + lane];
        acc.x += v.x; acc.y += v.y; acc.z += v.z; acc.w += v.w;
        if (lane == 0) s += g_eas[j];
    }
    g_aggr[w * 32 + lane] = acc;
    if (lane == 0) g_s[w] = s;
}

// ---------------------------------------------------------------------------
// Fused GEMM + epilogue:  out = relu( x@W1 + aggr@W2 + s*v3 )
// Block: 256 threads, 64 rows x 128 cols. Smem: W2 (64KB) + aggr tile^T (32KB).
// Mainloop uses fma.rn.f32x2: accumulators paired along ROW pairs so the A
// operands load pre-packed from shared memory (consecutive rows).
// ---------------------------------------------------------------------------
__global__ void gemm_fused_kernel(const float* __restrict__ x,
                                  const float* __restrict__ W1,
                                  const float* __restrict__ W2,
                                  float* __restrict__ out, int n) {
    extern __shared__ float sm[];
    float* Bs = sm;            // [128][128] = W2
    float* As = sm + H * H;    // [128][64]  = aggr tile (k-major)
    const int t = threadIdx.x;
    const int rbase = blockIdx.x * 64;

    for (int i = t; i < H * H / 4; i += 256)
        ((float4*)Bs)[i] = ((const float4*)W2)[i];

    for (int i = t; i < 64 * 32; i += 256) {
        int row = i >> 5;
        int kq  = i & 31;
        int r = rbase + row;
        float4 v = (r < n) ? g_aggr[r * 32 + kq]
                           : make_float4(0.f, 0.f, 0.f, 0.f);
        As[(4 * kq + 0) * 64 + row] = v.x;
        As[(4 * kq + 1) * 64 + row] = v.y;
        As[(4 * kq + 2) * 64 + row] = v.z;
        As[(4 * kq + 3) * 64 + row] = v.w;
    }
    __syncthreads();

    const int lane = t & 31;
    const int wid  = t >> 5;
    const int r0   = wid * 8;   // 8 consecutive rows -> 4 packed pairs
    const int c0   = lane * 4;  // 4 cols

    // accp[rp][c]: rows (r0+2rp, r0+2rp+1), col c0+c
    unsigned long long accp[4][4];
#pragma unroll
    for (int rp = 0; rp < 4; ++rp)
#pragma unroll
        for (int c = 0; c < 4; ++c) accp[rp][c] = 0ULL;

#pragma unroll 4
    for (int k = 0; k < H; ++k) {
        const float4 b = *(const float4*)&Bs[k * H + c0];
        unsigned long long bp[4] = {pack2(b.x), pack2(b.y), pack2(b.z), pack2(b.w)};
        const unsigned long long* ap =
            (const unsigned long long*)&As[k * 64 + r0];  // 4 pre-packed row pairs
        unsigned long long a0 = ap[0], a1 = ap[1], a2 = ap[2], a3 = ap[3];
#pragma unroll
        for (int c = 0; c < 4; ++c) {
            ffma2(accp[0][c], a0, bp[c]);
            ffma2(accp[1][c], a1, bp[c]);
            ffma2(accp[2][c], a2, bp[c]);
            ffma2(accp[3][c], a3, bp[c]);
        }
    }

    // epilogue: + x@W1 + s*v3, relu, store
    float4 v3v = g_v3[lane];
#pragma unroll
    for (int rp = 0; rp < 4; ++rp) {
        float lo[4], hi[4];
#pragma unroll
        for (int c = 0; c < 4; ++c) unpack2(accp[rp][c], lo[c], hi[c]);
#pragma unroll
        for (int half = 0; half < 2; ++half) {
            int r = rbase + r0 + 2 * rp + half;
            if (r >= n) continue;
            float4 o;
            if (half == 0) { o.x = lo[0]; o.y = lo[1]; o.z = lo[2]; o.w = lo[3]; }
            else           { o.x = hi[0]; o.y = hi[1]; o.z = hi[2]; o.w = hi[3]; }
            float s = g_s[r];
            o.x += s * v3v.x; o.y += s * v3v.y; o.z += s * v3v.z; o.w += s * v3v.w;

            float4 xv0 = ((const float4*)x)[r * 2];
            float4 xv1 = ((const float4*)x)[r * 2 + 1];
            float xk[8] = {xv0.x, xv0.y, xv0.z, xv0.w, xv1.x, xv1.y, xv1.z, xv1.w};
#pragma unroll
            for (int k = 0; k < 8; ++k) {
                float4 wv = ((const float4*)W1)[k * 32 + lane];
                o.x += xk[k] * wv.x;
                o.y += xk[k] * wv.y;
                o.z += xk[k] * wv.z;
                o.w += xk[k] * wv.w;
            }
            o.x = o.x > 0.f ? o.x : 0.f;
            o.y = o.y > 0.f ? o.y : 0.f;
            o.z = o.z > 0.f ? o.z : 0.f;
            o.w = o.w > 0.f ? o.w : 0.f;
            ((float4*)out)[r * 32 + lane] = o;
        }
    }
}

// ---------------------------------------------------------------------------
extern "C" void kernel_launch(void* const* d_in, const int* in_sizes, int n_in,
                              void* d_out, int out_size) {
    const float* x   = (const float*)d_in[0];
    const void*  ei  = d_in[1];                 // int32 or int64 (device-detected)
    const float* ea  = (const float*)d_in[2];
    const float* nb  = (const float*)d_in[3];
    const float* W1  = (const float*)d_in[4];
    const float* W2  = (const float*)d_in[5];
    const float* W3  = (const float*)d_in[6];
    const float* W4  = (const float*)d_in[7];
    float* out = (float*)d_out;

    const int n = in_sizes[0] / 8;   // 50000
    const int e = in_sizes[2];       // 800000
    const int nb_scan = (n + SCAN_B - 1) / SCAN_B;   // 196 <= 256

    const int smem = (H * H + H * 64) * sizeof(float);  // 98304 B
    cudaFuncSetAttribute(gemm_fused_kernel,
                         cudaFuncAttributeMaxDynamicSharedMemorySize, smem);

    zero_cnt_kernel<<<(n + 255) / 256, 256>>>(n);
    v3_kernel<<<1, 128>>>(W4, W3);
    hist_kernel<<<(e + 255) / 256, 256>>>(ei, e, n);
    scan1_kernel<<<nb_scan, SCAN_B>>>(n);
    scan3_kernel<<<nb_scan, SCAN_B>>>(n, nb_scan);
    fill_kernel<<<(e + 255) / 256, 256>>>(ei, ea, e, n);

    int aggr_blocks = (n * 32 + 255) / 256;
    aggr_kernel<<<aggr_blocks, 256>>>(nb, n);

    gemm_fused_kernel<<<(n + 63) / 64, 256, smem>>>(x, W1, W2, out, n);
}

// round 6
// speedup vs baseline: 1.6064x; 1.0414x over previous
#include <cuda_runtime.h>
#include <cuda_fp16.h>
#include <cstdint>

#define NMAX 50000
#define EMAX 800000
#define H 128

// ---------------- scratch (__device__ globals) ------------------------------
__device__ float4 g_aggr[NMAX * (H / 4)];  // segment-sum of nb rows (fp32)
__device__ uint2  g_nbh[NMAX * 32];        // node_embedding as fp16 (256B/row)
__device__ float  g_s[NMAX];               // per-node sum of edge_attr
__device__ float4 g_v3[H / 4];             // relu(W4) @ W3
__device__ int    g_cnt[NMAX];             // degree counts -> fill cursors
__device__ int    g_off[NMAX + 1];         // CSR row offsets
__device__ int    g_bsum[64];              // per-block sums for scan (49 used)
__device__ int    g_cols[EMAX];            // CSR column indices

// ---------------------------------------------------------------------------
__device__ __forceinline__ unsigned long long pack2(float v) {
    unsigned long long r;
    asm("mov.b64 %0, {%1, %1};" : "=l"(r) : "f"(v));
    return r;
}
__device__ __forceinline__ void unpack2(unsigned long long p, float& lo, float& hi) {
    asm("mov.b64 {%0, %1}, %2;" : "=f"(lo), "=f"(hi) : "l"(p));
}
__device__ __forceinline__ void ffma2(unsigned long long& d,
                                      unsigned long long a,
                                      unsigned long long b) {
    asm("fma.rn.f32x2 %0, %1, %2, %0;" : "+l"(d) : "l"(a), "l"(b));
}

__device__ __forceinline__ void load_edge(const void* __restrict__ ei, int e,
                                          int idx, int& r, int& c) {
    const int* p32 = (const int*)ei;
    bool is64 = (p32[1] | p32[3] | p32[5] | p32[7]) == 0;  // int64 => odd words 0
    if (is64) {
        const long long* p64 = (const long long*)ei;
        r = (int)p64[idx];
        c = (int)p64[e + idx];
    } else {
        r = p32[idx];
        c = p32[e + idx];
    }
}

// ---------------------------------------------------------------------------
// Prep: zero cnt/s, convert nb -> fp16 table, v3 = relu(W4)@W3 (block 0).
// ---------------------------------------------------------------------------
__global__ void prep_kernel(const float* __restrict__ nb,
                            const float* __restrict__ W4,
                            const float* __restrict__ W3, int n) {
    int i = blockIdx.x * blockDim.x + threadIdx.x;
    if (i < n) { g_cnt[i] = 0; g_s[i] = 0.f; }
    if (i < n * 32) {
        float4 v = ((const float4*)nb)[i];
        __half2 h0 = __floats2half2_rn(v.x, v.y);
        __half2 h1 = __floats2half2_rn(v.z, v.w);
        uint2 u;
        u.x = *(unsigned*)&h0;
        u.y = *(unsigned*)&h1;
        g_nbh[i] = u;
    }
    if (blockIdx.x == 0 && threadIdx.x < H) {
        int j = threadIdx.x;
        float acc = 0.f;
#pragma unroll 8
        for (int c = 0; c < H; ++c) {
            float w = W4[c];
            w = w > 0.f ? w : 0.f;
            acc += w * W3[c * H + j];
        }
        ((float*)g_v3)[j] = acc;
    }
}

// ---------------------------------------------------------------------------
// Histogram of destination rows + edge-attr scalar sums.
// ---------------------------------------------------------------------------
__global__ void hist_kernel(const void* __restrict__ ei,
                            const float* __restrict__ ea, int e, int n) {
    int i = blockIdx.x * blockDim.x + threadIdx.x;
    if (i >= e) return;
    int r, c;
    load_edge(ei, e, i, r, c);
    if ((unsigned)r < (unsigned)n) {
        atomicAdd(&g_cnt[r], 1);
        atomicAdd(&g_s[r], ea[i]);
    }
}

// ---------------------------------------------------------------------------
// Scan phase 1: per-block sums. Block covers 1024 counts (256 thr x int4).
// ---------------------------------------------------------------------------
__global__ void scan1_kernel(int n4) {
    __shared__ int ws[8];
    int t = threadIdx.x;
    int i = blockIdx.x * 256 + t;
    int4 v = (i < n4) ? ((const int4*)g_cnt)[i] : make_int4(0, 0, 0, 0);
    int s = v.x + v.y + v.z + v.w;
#pragma unroll
    for (int o = 16; o > 0; o >>= 1) s += __shfl_down_sync(0xffffffffu, s, o);
    if ((t & 31) == 0) ws[t >> 5] = s;
    __syncthreads();
    if (t == 0) {
        int a = 0;
#pragma unroll
        for (int k = 0; k < 8; ++k) a += ws[k];
        g_bsum[blockIdx.x] = a;
    }
}

// ---------------------------------------------------------------------------
// Scan phase 2: scan block sums in every block, local scan, write offsets.
// Block covers 1024 counts (256 thr x int4).
// ---------------------------------------------------------------------------
__global__ void scan3_kernel(int n, int n4, int nbs) {
    __shared__ int bs[64];
    __shared__ int ts[256];
    int t = threadIdx.x;
    int i = blockIdx.x * 256 + t;

    if (t < 64) bs[t] = (t < nbs) ? g_bsum[t] : 0;
    __syncthreads();
#pragma unroll
    for (int d = 1; d < 64; d <<= 1) {
        int v = (t < 64 && t >= d) ? bs[t - d] : 0;
        __syncthreads();
        if (t < 64) bs[t] += v;
        __syncthreads();
    }
    int base  = (blockIdx.x == 0) ? 0 : bs[blockIdx.x - 1];
    int total = bs[nbs - 1];

    int4 v = (i < n4) ? ((const int4*)g_cnt)[i] : make_int4(0, 0, 0, 0);
    int tot = v.x + v.y + v.z + v.w;
    ts[t] = tot;
    __syncthreads();
#pragma unroll
    for (int d = 1; d < 256; d <<= 1) {
        int x = (t >= d) ? ts[t - d] : 0;
        __syncthreads();
        ts[t] += x;
        __syncthreads();
    }
    if (i < n4) {
        int o0 = base + ts[t] - tot;
        int o1 = o0 + v.x, o2 = o1 + v.y, o3 = o2 + v.z;
        int4 offs = make_int4(o0, o1, o2, o3);
        ((int4*)g_off)[i] = offs;   // g_off[4i..4i+3]
        ((int4*)g_cnt)[i] = offs;   // cursors
    }
    if (blockIdx.x == 0 && t == 0) g_off[n] = total;
}

// ---------------------------------------------------------------------------
__global__ void fill_kernel(const void* __restrict__ ei, int e, int n) {
    int i = blockIdx.x * blockDim.x + threadIdx.x;
    if (i >= e) return;
    int r, c;
    load_edge(ei, e, i, r, c);
    if ((unsigned)r >= (unsigned)n || (unsigned)c >= (unsigned)n) return;
    int pos = atomicAdd(&g_cnt[r], 1);
    g_cols[pos] = c;
}

// ---------------------------------------------------------------------------
// Aggregate: warp per row, fp16 gathers (256B/row), fp32 accumulate.
// ---------------------------------------------------------------------------
__global__ void aggr_kernel(int n) {
    int w    = (blockIdx.x * blockDim.x + threadIdx.x) >> 5;
    int lane = threadIdx.x & 31;
    if (w >= n) return;

    int beg = g_off[w], end = g_off[w + 1];
    float4 acc = make_float4(0.f, 0.f, 0.f, 0.f);
    int j = beg;
    for (; j + 4 <= end; j += 4) {
        int c0 = g_cols[j], c1 = g_cols[j + 1], c2 = g_cols[j + 2], c3 = g_cols[j + 3];
        uint2 u0 = g_nbh[c0 * 32 + lane];
        uint2 u1 = g_nbh[c1 * 32 + lane];
        uint2 u2 = g_nbh[c2 * 32 + lane];
        uint2 u3 = g_nbh[c3 * 32 + lane];
#pragma unroll
        for (int q = 0; q < 4; ++q) {
            uint2 u = (q == 0) ? u0 : (q == 1) ? u1 : (q == 2) ? u2 : u3;
            float2 a = __half22float2(*(__half2*)&u.x);
            float2 b = __half22float2(*(__half2*)&u.y);
            acc.x += a.x; acc.y += a.y; acc.z += b.x; acc.w += b.y;
        }
    }
    for (; j < end; ++j) {
        int c = g_cols[j];
        uint2 u = g_nbh[c * 32 + lane];
        float2 a = __half22float2(*(__half2*)&u.x);
        float2 b = __half22float2(*(__half2*)&u.y);
        acc.x += a.x; acc.y += a.y; acc.z += b.x; acc.w += b.y;
    }
    g_aggr[w * 32 + lane] = acc;
}

// ---------------------------------------------------------------------------
// Fused GEMM + epilogue:  out = relu( x@W1 + aggr@W2 + s*v3 )
// 256 thr, 64 rows x 128 cols, FFMA2 mainloop (A pre-packed row pairs).
// ---------------------------------------------------------------------------
__global__ void gemm_fused_kernel(const float* __restrict__ x,
                                  const float* __restrict__ W1,
                                  const float* __restrict__ W2,
                                  float* __restrict__ out, int n) {
    extern __shared__ float sm[];
    float* Bs = sm;            // [128][128] = W2
    float* As = sm + H * H;    // [128][64]  = aggr tile (k-major)
    const int t = threadIdx.x;
    const int rbase = blockIdx.x * 64;

    for (int i = t; i < H * H / 4; i += 256)
        ((float4*)Bs)[i] = ((const float4*)W2)[i];

    for (int i = t; i < 64 * 32; i += 256) {
        int row = i >> 5;
        int kq  = i & 31;
        int r = rbase + row;
        float4 v = (r < n) ? g_aggr[r * 32 + kq]
                           : make_float4(0.f, 0.f, 0.f, 0.f);
        As[(4 * kq + 0) * 64 + row] = v.x;
        As[(4 * kq + 1) * 64 + row] = v.y;
        As[(4 * kq + 2) * 64 + row] = v.z;
        As[(4 * kq + 3) * 64 + row] = v.w;
    }
    __syncthreads();

    const int lane = t & 31;
    const int wid  = t >> 5;
    const int r0   = wid * 8;
    const int c0   = lane * 4;

    unsigned long long accp[4][4];
#pragma unroll
    for (int rp = 0; rp < 4; ++rp)
#pragma unroll
        for (int c = 0; c < 4; ++c) accp[rp][c] = 0ULL;

#pragma unroll 4
    for (int k = 0; k < H; ++k) {
        const float4 b = *(const float4*)&Bs[k * H + c0];
        unsigned long long bp[4] = {pack2(b.x), pack2(b.y), pack2(b.z), pack2(b.w)};
        const unsigned long long* ap =
            (const unsigned long long*)&As[k * 64 + r0];
        unsigned long long a0 = ap[0], a1 = ap[1], a2 = ap[2], a3 = ap[3];
#pragma unroll
        for (int c = 0; c < 4; ++c) {
            ffma2(accp[0][c], a0, bp[c]);
            ffma2(accp[1][c], a1, bp[c]);
            ffma2(accp[2][c], a2, bp[c]);
            ffma2(accp[3][c], a3, bp[c]);
        }
    }

    float4 v3v = g_v3[lane];
#pragma unroll
    for (int rp = 0; rp < 4; ++rp) {
        float lo[4], hi[4];
#pragma unroll
        for (int c = 0; c < 4; ++c) unpack2(accp[rp][c], lo[c], hi[c]);
#pragma unroll
        for (int half = 0; half < 2; ++half) {
            int r = rbase + r0 + 2 * rp + half;
            if (r >= n) continue;
            float4 o;
            if (half == 0) { o.x = lo[0]; o.y = lo[1]; o.z = lo[2]; o.w = lo[3]; }
            else           { o.x = hi[0]; o.y = hi[1]; o.z = hi[2]; o.w = hi[3]; }
            float s = g_s[r];
            o.x += s * v3v.x; o.y += s * v3v.y; o.z += s * v3v.z; o.w += s * v3v.w;

            float4 xv0 = ((const float4*)x)[r * 2];
            float4 xv1 = ((const float4*)x)[r * 2 + 1];
            float xk[8] = {xv0.x, xv0.y, xv0.z, xv0.w, xv1.x, xv1.y, xv1.z, xv1.w};
#pragma unroll
            for (int k = 0; k < 8; ++k) {
                float4 wv = ((const float4*)W1)[k * 32 + lane];
                o.x += xk[k] * wv.x;
                o.y += xk[k] * wv.y;
                o.z += xk[k] * wv.z;
                o.w += xk[k] * wv.w;
            }
            o.x = o.x > 0.f ? o.x : 0.f;
            o.y = o.y > 0.f ? o.y : 0.f;
            o.z = o.z > 0.f ? o.z : 0.f;
            o.w = o.w > 0.f ? o.w : 0.f;
            ((float4*)out)[r * 32 + lane] = o;
        }
    }
}

// ---------------------------------------------------------------------------
extern "C" void kernel_launch(void* const* d_in, const int* in_sizes, int n_in,
                              void* d_out, int out_size) {
    const float* x   = (const float*)d_in[0];
    const void*  ei  = d_in[1];                 // int32 or int64 (device-detected)
    const float* ea  = (const float*)d_in[2];
    const float* nb  = (const float*)d_in[3];
    const float* W1  = (const float*)d_in[4];
    const float* W2  = (const float*)d_in[5];
    const float* W3  = (const float*)d_in[6];
    const float* W4  = (const float*)d_in[7];
    float* out = (float*)d_out;

    const int n  = in_sizes[0] / 8;   // 50000
    const int e  = in_sizes[2];       // 800000
    const int n4 = (n + 3) / 4;       // 12500
    const int nbs = (n4 + 255) / 256; // 49 scan blocks

    const int smem = (H * H + H * 64) * sizeof(float);  // 98304 B
    cudaFuncSetAttribute(gemm_fused_kernel,
                         cudaFuncAttributeMaxDynamicSharedMemorySize, smem);

    prep_kernel<<<(n * 32 + 255) / 256, 256>>>(nb, W4, W3, n);
    hist_kernel<<<(e + 255) / 256, 256>>>(ei, ea, e, n);
    scan1_kernel<<<nbs, 256>>>(n4);
    scan3_kernel<<<nbs, 256>>>(n, n4, nbs);
    fill_kernel<<<(e + 255) / 256, 256>>>(ei, e, n);
    aggr_kernel<<<(n * 32 + 255) / 256, 256>>>(n);
    gemm_fused_kernel<<<(n + 63) / 64, 256, smem>>>(x, W1, W2, out, n);
}